// round 17
// baseline (speedup 1.0000x reference)
#include <cuda_runtime.h>
#include <float.h>
#include <math.h>

// CropRoi: f (B=4,64,32,32,32) f32; proposals (N=96,8) f32; out (96,64,7,7,7).
// Box: c0 = max(floor((c-s/2)/4),0), c1 = min(ceil((c+s/2)/4),32); windows per
// axis are 1..3 wide, in-range -> plain max (clip+mask is a no-op).
//
// Inverted structure: block = (b, c). Stage the whole 32^3 slab (128KB) into
// smem ONCE (chip-wide = 32MB = compulsory-minimum read of f, fully coalesced
// float4), stage this batch's proposal descriptors into smem, then sweep all
// ~24 proposals from smem at LDS latency (29cyc) with warp-uniform clamped
// taps (no divergence replay; smem duplicates broadcast for free).
// Per-batch proposal lists built deterministically (no atomics) in precompute.

#define RBINS 7
#define NBINS 343
#define FDIM 32
#define MAXN 128
#define MAXB 8
#define SLAB 32768                 // 32^3 floats
#define MAXP_S 48                  // descs staged in smem (mean count = 24)

__device__ int g_desc[MAXN * NBINS];   // start:15 | nd:2 | nh:2 | nw:2
__device__ int g_list[MAXB * MAXN];    // proposal ids per batch
__device__ int g_cnt[MAXB];

__global__ void precompute_kernel(const float* __restrict__ props, int N)
{
    const int n = blockIdx.x;
    const int t = threadIdx.x;

    __shared__ int bs[MAXN];
    for (int m = t; m < N; m += blockDim.x)
        bs[m] = (int)props[m * 8];
    __syncthreads();

    const float* p = props + n * 8;
    int c0[3], L[3];
#pragma unroll
    for (int ax = 0; ax < 3; ++ax) {
        const float ce = p[2 + ax], si = p[5 + ax];
        int lo = (int)floorf((ce - si * 0.5f) * 0.25f);
        int hi = (int)ceilf ((ce + si * 0.5f) * 0.25f);
        lo = max(lo, 0); hi = min(hi, FDIM);
        c0[ax] = lo;
        L[ax]  = max(hi - lo, 1);
    }

    if (t < NBINS) {
        const int k = t % RBINS;
        const int j = (t / RBINS) % RBINS;
        const int i = t / (RBINS * RBINS);

        const int ds = (i * L[0]) / RBINS, de = ((i + 1) * L[0] + RBINS - 1) / RBINS;
        const int hs = (j * L[1]) / RBINS, he = ((j + 1) * L[1] + RBINS - 1) / RBINS;
        const int ws = (k * L[2]) / RBINS, we = ((k + 1) * L[2] + RBINS - 1) / RBINS;

        const int start = ((c0[0] + ds) * FDIM + (c0[1] + hs)) * FDIM + (c0[2] + ws);
        g_desc[n * NBINS + t] =
            start | ((de - ds - 1) << 15) | ((he - hs - 1) << 17) | ((we - ws - 1) << 19);
    }

    if (t == 0) {                     // deterministic list slot (no atomics)
        const int bn = bs[n];
        int pos = 0;
        for (int m = 0; m < n; ++m) pos += (bs[m] == bn);
        g_list[bn * MAXN + pos] = n;
    }
    if (n == 0 && t < MAXB) {
        int cnt = 0;
        for (int m = 0; m < N; ++m) cnt += (bs[m] == t);
        g_cnt[t] = cnt;
    }
}

__global__ __launch_bounds__(512)
void pool_kernel(const float* __restrict__ f, float* __restrict__ out)
{
    extern __shared__ char smx[];
    float* slab    = (float*)smx;                                  // 128 KB
    int*   descs_s = (int*)(smx + SLAB * 4);                       // 64.3 KB
    int*   list_s  = (int*)(smx + SLAB * 4 + MAXP_S * NBINS * 4);  // 512 B

    const int b = blockIdx.x;       // batch
    const int c = blockIdx.y;       // channel
    const int tid = threadIdx.x;

    const int cnt = g_cnt[b];

    for (int s = tid; s < cnt; s += 512)
        list_s[s] = g_list[b * MAXN + s];
    __syncthreads();

    // ---- stage the (b,c) slab: 8192 float4, fully coalesced ----
    const float4* fs = (const float4*)(f + (((size_t)(b * 64 + c)) << 15));
    float4* ss = (float4*)slab;
#pragma unroll 4
    for (int i = tid; i < SLAB / 4; i += 512)
        ss[i] = __ldg(fs + i);

    // ---- stage descriptors of this batch's proposals ----
    const int nstage = min(cnt, MAXP_S);
    for (int i = tid; i < nstage * NBINS; i += 512) {
        const int sidx = i / NBINS;              // const-div -> mul/shift
        const int bin  = i - sidx * NBINS;
        descs_s[i] = g_desc[list_s[sidx] * NBINS + bin];
    }
    __syncthreads();

    // ---- sweep proposals from smem (warps 0..10; full warps for REDUX) ----
    if (tid < 352) {
        const int t   = min(tid, NBINS - 1);
        const bool act = tid < NBINS;

        for (int s = 0; s < cnt; ++s) {
            const int n = list_s[s];
            const int desc = (s < MAXP_S) ? descs_s[s * NBINS + t]
                                          : __ldg(&g_desc[n * NBINS + t]);
            const int start =  desc        & 0x7FFF;
            const int nd    = (desc >> 15) & 3;
            const int nh    = (desc >> 17) & 3;
            const int nw    = (desc >> 19) & 3;

            const int ndw = __reduce_max_sync(0xFFFFFFFFu, nd);
            const int nhw = __reduce_max_sync(0xFFFFFFFFu, nh);
            const int nww = __reduce_max_sync(0xFFFFFFFFu, nw);

            float m = -FLT_MAX;
            for (int d = 0; d <= ndw; ++d) {
                const int doff = start + (min(d, nd) << 10);
                for (int h = 0; h <= nhw; ++h) {
                    const int hoff = doff + (min(h, nh) << 5);
                    for (int w = 0; w <= nww; ++w)
                        m = fmaxf(m, slab[hoff + min(w, nw)]);
                }
            }

            if (act)
                out[((size_t)(n * 64 + c)) * NBINS + tid] = m;
        }
    }
}

extern "C" void kernel_launch(void* const* d_in, const int* in_sizes, int n_in,
                              void* d_out, int out_size)
{
    const float* f     = (const float*)d_in[0];
    const float* props = (const float*)d_in[2];
    float* out = (float*)d_out;

    const int N = in_sizes[2] / 8;          // 96 proposals
    const int B = in_sizes[0] >> 21;        // f elems / (64*32768) = 4 batches

    const int smem = SLAB * 4 + MAXP_S * NBINS * 4 + MAXN * 4;  // ~194 KB
    cudaFuncSetAttribute(pool_kernel,
                         cudaFuncAttributeMaxDynamicSharedMemorySize, smem);

    precompute_kernel<<<N, 352>>>(props, N);
    pool_kernel<<<dim3(B, 64), 512, smem>>>(f, out);
}